// round 15
// baseline (speedup 1.0000x reference)
#include <cuda_runtime.h>
#include <cstdint>
#include <cstddef>

// ---------------- problem constants ----------------
#define BB 2
#define CC 256
#define HW 16384
#define MPIX 32768
#define NCLS 80
#define NMS_CAND 1000
#define MAX_DET 100
#define STG16 (16 * 132)

// ---------------- scratch ----------------
__device__ float g_WF[96 * 256];     // full weights: rows 0..79 cls, 80..83 box, 84 obj, 85..95 zero
__device__ float g_bF[96];
__device__ float g_score[MPIX];
__device__ int   g_label[MPIX];
__device__ float g_boxes[(size_t)MPIX * 4];

__device__ __forceinline__ float sigmoidf_(float x) { return 1.f / (1.f + expf(-x)); }

// ---------------- single-kernel full-network composition, 1024 threads, 4-way j-split ----------------
__global__ void __launch_bounds__(1024) wfull_k(
    const float* __restrict__ cwin, const float* __restrict__ cbin,
    const float* __restrict__ cwh,  const float* __restrict__ cbh,
    const float* __restrict__ cwo,  const float* __restrict__ cbo,
    const float* __restrict__ owin, const float* __restrict__ obin,
    const float* __restrict__ owh,  const float* __restrict__ obh,
    const float* __restrict__ owo,  const float* __restrict__ obo,
    const float* __restrict__ bwin, const float* __restrict__ bbin,
    const float* __restrict__ bwh,  const float* __restrict__ bbh,
    const float* __restrict__ bwo,  const float* __restrict__ bbo)
{
    __shared__ float T[2][4][256];
    __shared__ float red[4][4][256];   // [q][r][t]
    __shared__ float tb[4];
    const int bid = blockIdx.x;        // 0..23 -> rows 4*bid..4*bid+3
    const int tid = threadIdx.x;
    const int t = tid & 255, q = tid >> 8;
    const int lane = tid & 31;

    const float *Whid, *bhid, *Win, *binp;
    if (bid < 20)      { Whid = cwh; bhid = cbh; Win = cwin; binp = cbin; }
    else if (bid == 20){ Whid = bwh; bhid = bbh; Win = bwin; binp = bbin; }
    else               { Whid = owh; bhid = obh; Win = owin; binp = obin; }

    if (q == 0) {
        #pragma unroll
        for (int r = 0; r < 4; r++) {
            int s = bid * 4 + r;
            float v = 0.f;
            if (s < 80)        v = cwo[(size_t)s * 256 + t];
            else if (s < 84)   v = bwo[(size_t)(s - 80) * 256 + t];
            else if (s == 84)  v = owo[t];
            T[0][r][t] = v;
        }
        if (t < 4) {
            int s = bid * 4 + t;
            float bv = 0.f;
            if (s < 80)        bv = cbo[s];
            else if (s < 84)   bv = bbo[s - 80];
            else if (s == 84)  bv = obo[0];
            tb[t] = bv;
        }
    }
    __syncthreads();

    int cur = 0;
    for (int l = 3; l >= 0; l--) {
        const float* W = Whid + (size_t)l * 65536;
        const float* bl = bhid + l * 256;
        if (q == 0) {
            float blv = bl[t];
            #pragma unroll
            for (int r = 0; r < 4; r++) {
                float pv = T[cur][r][t] * blv;
                #pragma unroll
                for (int off = 16; off > 0; off >>= 1)
                    pv += __shfl_xor_sync(0xffffffffu, pv, off);
                if (lane == 0) atomicAdd(&tb[r], pv);
            }
        }
        float a0 = 0.f, a1 = 0.f, a2 = 0.f, a3 = 0.f;
        const int j0 = q * 64;
        #pragma unroll 8
        for (int jj = 0; jj < 64; jj++) {
            int j = j0 + jj;
            float w = W[(size_t)j * 256 + t];
            a0 = fmaf(T[cur][0][j], w, a0);
            a1 = fmaf(T[cur][1][j], w, a1);
            a2 = fmaf(T[cur][2][j], w, a2);
            a3 = fmaf(T[cur][3][j], w, a3);
        }
        red[q][0][t] = a0; red[q][1][t] = a1; red[q][2][t] = a2; red[q][3][t] = a3;
        __syncthreads();
        if (q == 0) {
            #pragma unroll
            for (int r = 0; r < 4; r++)
                T[cur ^ 1][r][t] = T[cur][r][t] +
                    ((red[0][r][t] + red[1][r][t]) + (red[2][r][t] + red[3][r][t]));
        }
        __syncthreads();
        cur ^= 1;
    }

    if (q == 0) {
        float bv = binp[t];
        #pragma unroll
        for (int r = 0; r < 4; r++) {
            float pv = T[cur][r][t] * bv;
            #pragma unroll
            for (int off = 16; off > 0; off >>= 1)
                pv += __shfl_xor_sync(0xffffffffu, pv, off);
            if (lane == 0) atomicAdd(&tb[r], pv);
        }
    }
    float a0 = 0.f, a1 = 0.f, a2 = 0.f, a3 = 0.f;
    const int j0 = q * 64;
    #pragma unroll 8
    for (int jj = 0; jj < 64; jj++) {
        int j = j0 + jj;
        float w = Win[(size_t)j * 256 + t];
        a0 = fmaf(T[cur][0][j], w, a0);
        a1 = fmaf(T[cur][1][j], w, a1);
        a2 = fmaf(T[cur][2][j], w, a2);
        a3 = fmaf(T[cur][3][j], w, a3);
    }
    red[q][0][t] = a0; red[q][1][t] = a1; red[q][2][t] = a2; red[q][3][t] = a3;
    __syncthreads();
    if (q == 0) {
        #pragma unroll
        for (int r = 0; r < 4; r++)
            g_WF[(size_t)(bid * 4 + r) * 256 + t] =
                (red[0][r][t] + red[1][r][t]) + (red[2][r][t] + red[3][r][t]);
        if (t < 4) g_bF[bid * 4 + t] = tb[t];
    }
}

// ---------------- fused full-network GEMM + decode ----------------
__global__ void __launch_bounds__(256) fdec_k(const float* __restrict__ feat) {
    extern __shared__ __align__(16) float sm[];
    float* As   = sm;                    // [16][132]
    float* Bsw  = sm + STG16;            // [16][100]
    float* sbias = sm + STG16 + 1600;    // 112
    float* slog = sm + STG16 + 1712;     // [128][97]

    const int m0 = blockIdx.x * 128;
    const int b = m0 >> 14;
    const int mm = m0 & (HW - 1);
    const int tid = threadIdx.x;
    const int tx = tid & 15, ty = tid >> 4;

    if (tid < 96) sbias[tid] = g_bF[tid];

    float acc[8][6];
    #pragma unroll
    for (int i = 0; i < 8; i++)
        #pragma unroll
        for (int j = 0; j < 6; j++) acc[i][j] = 0.f;

    #pragma unroll 1
    for (int p = 0; p < 16; p++) {
        __syncthreads();
        #pragma unroll
        for (int lq = 0; lq < 2; lq++) {
            int idx = tid + lq * 256;
            int k = idx >> 5, c4 = idx & 31;
            *(float4*)&As[k * 132 + c4 * 4] =
                *(const float4*)(feat + ((size_t)(b * CC + p * 16 + k)) * HW + mm + c4 * 4);
        }
        #pragma unroll
        for (int lq = 0; lq < 6; lq++) {
            int idx = tid + lq * 256;
            int k = idx & 15, slot = idx >> 4;
            Bsw[k * 100 + slot] = g_WF[(size_t)slot * 256 + p * 16 + k];
        }
        __syncthreads();

        #pragma unroll
        for (int kk = 0; kk < 16; kk++) {
            float4 a0 = *(const float4*)&As[kk * 132 + ty * 8];
            float4 a1 = *(const float4*)&As[kk * 132 + ty * 8 + 4];
            float a[8] = {a0.x, a0.y, a0.z, a0.w, a1.x, a1.y, a1.z, a1.w};
            float bv[6];
            #pragma unroll
            for (int j = 0; j < 6; j++) bv[j] = Bsw[kk * 100 + tx + 16 * j];
            #pragma unroll
            for (int i = 0; i < 8; i++)
                #pragma unroll
                for (int j = 0; j < 6; j++)
                    acc[i][j] = fmaf(a[i], bv[j], acc[i][j]);
        }
    }

    __syncthreads();
    #pragma unroll
    for (int i = 0; i < 8; i++)
        #pragma unroll
        for (int j = 0; j < 6; j++) {
            int col = tx + 16 * j;
            slog[(ty * 8 + i) * 97 + col] = acc[i][j] + sbias[col];
        }
    __syncthreads();

    if (tid < 128) {
        const float* lg = &slog[tid * 97];
        float objp = sigmoidf_(lg[84]);
        float best = -1.f; int bl = 0;
        #pragma unroll 4
        for (int c = 0; c < NCLS; c++) {
            float pr = sigmoidf_(lg[c]) * objp;
            if (pr > best) { best = pr; bl = c; }
        }
        int n = m0 + tid;
        g_score[n] = best;
        g_label[n] = bl;
        int hw = n & (HW - 1);
        int h = hw >> 7, w = hw & 127;
        float px = (w + 0.5f) * 8.f;
        float py = (h + 0.5f) * 8.f;
        float l = expf(lg[80]) * 8.f;
        float t = expf(lg[81]) * 8.f;
        float r = expf(lg[82]) * 8.f;
        float d = expf(lg[83]) * 8.f;
        g_boxes[(size_t)n * 4 + 0] = px - l;
        g_boxes[(size_t)n * 4 + 1] = py - t;
        g_boxes[(size_t)n * 4 + 2] = px + r;
        g_boxes[(size_t)n * 4 + 3] = py + d;
    }
}

// ---------------- fused backend: topk + NMS + select, one block per batch ----------------
// smem layout (bytes):
//   [0, 32768)            skey  ull[4096]
//   [32768, 160768)       mask  u32[1000*32]
//   [160768, 176768)      cbox  f32[1000*4]
//   [176768, 180768)      csc   f32[1000]
//   [180768, 184768)      clab  i32[1000]
//   [184768, 188864)      ps    i32[1024]
//   [188864, 189888)      hist  i32[256]
#define POST_SMEM 189888
__global__ void __launch_bounds__(1024) post_k(float* __restrict__ out) {
    extern __shared__ __align__(16) unsigned char smraw[];
    unsigned long long* skey = (unsigned long long*)smraw;
    unsigned* mask = (unsigned*)(smraw + 32768);
    float* cbox = (float*)(smraw + 160768);
    float* csc  = (float*)(smraw + 176768);
    int*   clab = (int*)(smraw + 180768);
    int*   ps   = (int*)(smraw + 184768);
    int*   hist = (int*)(smraw + 188864);
    __shared__ int s_b1, s_n1, s_thr, s_cnt, s_total;
    __shared__ unsigned keepw[32];

    const int b = blockIdx.x;
    const int tid = threadIdx.x;
    const int lane = tid & 31;

    // ---- level-1 histogram (warp-aggregated) ----
    if (tid < 256) hist[tid] = 0;
    __syncthreads();
    for (int i = tid; i < HW; i += 1024) {
        unsigned u = __float_as_uint(g_score[b * HW + i]);
        int bin = u >> 24;
        unsigned mm = __match_any_sync(0xffffffffu, bin);
        if (lane == (__ffs(mm) - 1)) atomicAdd(&hist[bin], __popc(mm));
    }
    __syncthreads();
    if (tid == 0) {
        int acc = 0; int bin = 255;
        for (; bin > 0; bin--) { if (acc + hist[bin] >= NMS_CAND) break; acc += hist[bin]; }
        s_b1 = bin; s_n1 = acc;
    }
    __syncthreads();
    int b1 = s_b1, n1 = s_n1;
    if (tid < 256) hist[tid] = 0;
    __syncthreads();
    // ---- level-2 histogram ----
    for (int i = tid; i < HW; i += 1024) {
        unsigned u = __float_as_uint(g_score[b * HW + i]);
        bool sel = ((int)(u >> 24) == b1);
        unsigned active = __ballot_sync(0xffffffffu, sel);
        if (sel) {
            int bin2 = (u >> 16) & 255;
            unsigned mm = __match_any_sync(active, bin2);
            if (lane == (__ffs(mm) - 1)) atomicAdd(&hist[bin2], __popc(mm));
        }
    }
    __syncthreads();
    if (tid == 0) {
        int acc = n1; int bin = 255;
        for (; bin > 0; bin--) { if (acc + hist[bin] >= NMS_CAND) break; acc += hist[bin]; }
        s_thr = (b1 << 8) | bin;
        s_cnt = 0;
    }
    __syncthreads();
    unsigned thr = (unsigned)s_thr;
    // ---- compaction ----
    for (int i = tid; i < HW; i += 1024) {
        unsigned u = __float_as_uint(g_score[b * HW + i]);
        bool pass = (u >> 16) >= thr;
        unsigned bal = __ballot_sync(0xffffffffu, pass);
        int base = 0;
        if (lane == 0 && bal) base = atomicAdd(&s_cnt, __popc(bal));
        base = __shfl_sync(0xffffffffu, base, 0);
        if (pass) {
            int pos = base + __popc(bal & ((1u << lane) - 1u));
            if (pos < 4096)
                skey[pos] = ((unsigned long long)(~u) << 32) | (unsigned)i;
        }
    }
    __syncthreads();
    int cnt = s_cnt < 4096 ? s_cnt : 4096;
    for (int i = tid; i < 4096; i += 1024)
        if (i >= cnt) skey[i] = 0xFFFFFFFFFFFFFFFFull;
    __syncthreads();
    // ---- bitonic sort 4096 ----
    for (int k = 2; k <= 4096; k <<= 1) {
        for (int j = k >> 1; j > 0; j >>= 1) {
            #pragma unroll
            for (int l = 0; l < 4; l++) {
                int i = tid + l * 1024;
                int ixj = i ^ j;
                if (ixj > i) {
                    bool up = ((i & k) == 0);
                    unsigned long long a = skey[i], c = skey[ixj];
                    if (up ? (a > c) : (a < c)) { skey[i] = c; skey[ixj] = a; }
                }
            }
            __syncthreads();
        }
    }
    // ---- extract candidates to smem ----
    if (tid < NMS_CAND) {
        unsigned long long key = skey[tid];
        int idx = (int)(unsigned)key;
        float s = __uint_as_float(~(unsigned)(key >> 32));
        int g = b * HW + idx;
        csc[tid] = s;
        clab[tid] = g_label[g];
        #pragma unroll
        for (int q = 0; q < 4; q++)
            cbox[tid * 4 + q] = g_boxes[(size_t)g * 4 + q];
    }
    __syncthreads();
    // ---- IoU suppression mask ----
    {
        int j = tid;
        float jx1 = 0.f, jy1 = 0.f, jx2 = 0.f, jy2 = 0.f, aj = 0.f;
        if (j < NMS_CAND) {
            jx1 = cbox[j * 4 + 0]; jy1 = cbox[j * 4 + 1];
            jx2 = cbox[j * 4 + 2]; jy2 = cbox[j * 4 + 3];
            aj = fmaxf(jx2 - jx1, 0.f) * fmaxf(jy2 - jy1, 0.f);
        }
        for (int i = 0; i < NMS_CAND; i++) {
            float ix1 = cbox[i * 4 + 0], iy1 = cbox[i * 4 + 1];
            float ix2 = cbox[i * 4 + 2], iy2 = cbox[i * 4 + 3];
            float ai = fmaxf(ix2 - ix1, 0.f) * fmaxf(iy2 - iy1, 0.f);
            bool pred = false;
            if (j < NMS_CAND && j > i) {
                float xx1 = fmaxf(ix1, jx1), yy1 = fmaxf(iy1, jy1);
                float xx2 = fminf(ix2, jx2), yy2 = fminf(iy2, jy2);
                float iw = fmaxf(xx2 - xx1, 0.f), ih = fmaxf(yy2 - yy1, 0.f);
                float inter = iw * ih;
                float iou = inter / (ai + aj - inter + 1e-6f);
                pred = iou > 0.65f;
            }
            unsigned m = __ballot_sync(0xffffffffu, pred);
            if (lane == 0)
                mask[i * 32 + (tid >> 5)] = m;
        }
    }
    __syncthreads();
    // ---- sequential reduce (warp 0) ----
    if (tid < 32) {
        unsigned removed = 0u;
        for (int i = 0; i < NMS_CAND; i++) {
            unsigned rw = __shfl_sync(0xffffffffu, removed, i >> 5);
            if (!((rw >> (i & 31)) & 1u))
                removed |= mask[i * 32 + lane];
        }
        keepw[lane] = ~removed;
    }
    __syncthreads();
    // ---- select ----
    int kept = 0;
    if (tid < NMS_CAND)
        kept = (keepw[tid >> 5] >> (tid & 31)) & 1;
    ps[tid] = kept;
    __syncthreads();
    for (int off = 1; off < 1024; off <<= 1) {
        int v = (tid >= off) ? ps[tid - off] : 0;
        __syncthreads();
        ps[tid] += v;
        __syncthreads();
    }
    if (tid == 1023) s_total = ps[1023];
    __syncthreads();
    int total = s_total;
    if (tid < NMS_CAND) {
        int excl = ps[tid] - kept;
        int pos = kept ? excl : total + (tid - excl);
        if (pos < MAX_DET) {
            out[(b * MAX_DET + pos) * 4 + 0] = cbox[tid * 4 + 0];
            out[(b * MAX_DET + pos) * 4 + 1] = cbox[tid * 4 + 1];
            out[(b * MAX_DET + pos) * 4 + 2] = cbox[tid * 4 + 2];
            out[(b * MAX_DET + pos) * 4 + 3] = cbox[tid * 4 + 3];
            out[BB * MAX_DET * 4 + b * MAX_DET + pos] = kept ? csc[tid] : 0.f;
            out[BB * MAX_DET * 5 + b * MAX_DET + pos] = (float)clab[tid];
        }
    }
}

// ---------------- launch ----------------
extern "C" void kernel_launch(void* const* d_in, const int* in_sizes, int n_in,
                              void* d_out, int out_size) {
    (void)in_sizes; (void)n_in; (void)out_size;
    const float* feat = (const float*)d_in[0];
    const float* cls_w_in  = (const float*)d_in[1];
    const float* cls_b_in  = (const float*)d_in[2];
    const float* cls_w_hid = (const float*)d_in[3];
    const float* cls_b_hid = (const float*)d_in[4];
    const float* cls_w_out = (const float*)d_in[5];
    const float* cls_b_out = (const float*)d_in[6];
    const float* obj_w_in  = (const float*)d_in[7];
    const float* obj_b_in  = (const float*)d_in[8];
    const float* obj_w_hid = (const float*)d_in[9];
    const float* obj_b_hid = (const float*)d_in[10];
    const float* obj_w_out = (const float*)d_in[11];
    const float* obj_b_out = (const float*)d_in[12];
    const float* box_w_in  = (const float*)d_in[13];
    const float* box_b_in  = (const float*)d_in[14];
    const float* box_w_hid = (const float*)d_in[15];
    const float* box_b_hid = (const float*)d_in[16];
    const float* box_w_out = (const float*)d_in[17];
    const float* box_b_out = (const float*)d_in[18];
    float* out = (float*)d_out;

    const int fdec_smem = (STG16 + 1712 + 128 * 97) * (int)sizeof(float);
    cudaFuncSetAttribute(fdec_k, cudaFuncAttributeMaxDynamicSharedMemorySize, fdec_smem);
    cudaFuncSetAttribute(post_k, cudaFuncAttributeMaxDynamicSharedMemorySize, POST_SMEM);

    // 0) single-kernel full-network composition -> WF[96][256], bF[96]
    wfull_k<<<24, 1024>>>(cls_w_in, cls_b_in, cls_w_hid, cls_b_hid, cls_w_out, cls_b_out,
                          obj_w_in, obj_b_in, obj_w_hid, obj_b_hid, obj_w_out, obj_b_out,
                          box_w_in, box_b_in, box_w_hid, box_b_hid, box_w_out, box_b_out);

    // 1) fused full-network GEMM + decode
    fdec_k<<<MPIX / 128, 256, fdec_smem>>>(feat);

    // 2) fused topk + NMS + select (one block per batch)
    post_k<<<BB, 1024, POST_SMEM>>>(out);
}

// round 16
// speedup vs baseline: 1.8906x; 1.8906x over previous
#include <cuda_runtime.h>
#include <cstdint>
#include <cstddef>

// ---------------- problem constants ----------------
#define BB 2
#define CC 256
#define HW 16384
#define MPIX 32768
#define NCLS 80
#define NMS_CAND 1000
#define MAX_DET 100
#define ATILE (16 * 132)
#define BTILE (16 * 100)

// ---------------- scratch ----------------
__device__ float g_WFT[256 * 96];    // transposed full weights: [k][slot]
__device__ float g_bF[96];
__device__ float g_score[MPIX];
__device__ int   g_label[MPIX];
__device__ float g_boxes[(size_t)MPIX * 4];
__device__ float g_cand_sc[BB * NMS_CAND];
__device__ int   g_cand_lab[BB * NMS_CAND];
__device__ float g_cand_box[BB * NMS_CAND * 4];
__device__ unsigned g_mask[(size_t)BB * NMS_CAND * 32];
__device__ unsigned g_keep[BB * 32];

__device__ __forceinline__ float sigmoidf_(float x) { return 1.f / (1.f + expf(-x)); }
__device__ __forceinline__ unsigned smem_addr(const void* p) {
    return (unsigned)__cvta_generic_to_shared(p);
}
__device__ __forceinline__ void cpasync16(unsigned dst, const float* src) {
    asm volatile("cp.async.cg.shared.global [%0], [%1], 16;\n" :: "r"(dst), "l"(src));
}
__device__ __forceinline__ void cp_commit() {
    asm volatile("cp.async.commit_group;\n" ::: "memory");
}
template <int N>
__device__ __forceinline__ void cp_wait() {
    asm volatile("cp.async.wait_group %0;\n" :: "n"(N) : "memory");
}

// ---------------- single-kernel full-network composition (256 threads, R14 version) ----------------
__global__ void __launch_bounds__(256) wfull_k(
    const float* __restrict__ cwin, const float* __restrict__ cbin,
    const float* __restrict__ cwh,  const float* __restrict__ cbh,
    const float* __restrict__ cwo,  const float* __restrict__ cbo,
    const float* __restrict__ owin, const float* __restrict__ obin,
    const float* __restrict__ owh,  const float* __restrict__ obh,
    const float* __restrict__ owo,  const float* __restrict__ obo,
    const float* __restrict__ bwin, const float* __restrict__ bbin,
    const float* __restrict__ bwh,  const float* __restrict__ bbh,
    const float* __restrict__ bwo,  const float* __restrict__ bbo)
{
    __shared__ float T[2][4][256];
    __shared__ float tb[4];
    const int bid = blockIdx.x;   // 0..23 -> slots 4*bid..4*bid+3
    const int t = threadIdx.x;    // 256
    const int lane = t & 31;

    const float *Whid, *bhid, *Win, *binp;
    if (bid < 20)      { Whid = cwh; bhid = cbh; Win = cwin; binp = cbin; }
    else if (bid == 20){ Whid = bwh; bhid = bbh; Win = bwin; binp = bbin; }
    else               { Whid = owh; bhid = obh; Win = owin; binp = obin; }

    #pragma unroll
    for (int r = 0; r < 4; r++) {
        int s = bid * 4 + r;
        float v = 0.f;
        if (s < 80)        v = cwo[(size_t)s * 256 + t];
        else if (s < 84)   v = bwo[(size_t)(s - 80) * 256 + t];
        else if (s == 84)  v = owo[t];
        T[0][r][t] = v;
    }
    if (t < 4) {
        int s = bid * 4 + t;
        float bv = 0.f;
        if (s < 80)        bv = cbo[s];
        else if (s < 84)   bv = bbo[s - 80];
        else if (s == 84)  bv = obo[0];
        tb[t] = bv;
    }
    __syncthreads();

    int cur = 0;
    for (int l = 3; l >= 0; l--) {
        const float* W = Whid + (size_t)l * 65536;
        const float* bl = bhid + l * 256;
        float blv = bl[t];
        #pragma unroll
        for (int r = 0; r < 4; r++) {
            float pv = T[cur][r][t] * blv;
            #pragma unroll
            for (int off = 16; off > 0; off >>= 1)
                pv += __shfl_xor_sync(0xffffffffu, pv, off);
            if (lane == 0) atomicAdd(&tb[r], pv);
        }
        float acc0 = 0.f, acc1 = 0.f, acc2 = 0.f, acc3 = 0.f;
        #pragma unroll 8
        for (int j = 0; j < 256; j++) {
            float w = W[(size_t)j * 256 + t];
            acc0 = fmaf(T[cur][0][j], w, acc0);
            acc1 = fmaf(T[cur][1][j], w, acc1);
            acc2 = fmaf(T[cur][2][j], w, acc2);
            acc3 = fmaf(T[cur][3][j], w, acc3);
        }
        T[cur ^ 1][0][t] = T[cur][0][t] + acc0;
        T[cur ^ 1][1][t] = T[cur][1][t] + acc1;
        T[cur ^ 1][2][t] = T[cur][2][t] + acc2;
        T[cur ^ 1][3][t] = T[cur][3][t] + acc3;
        __syncthreads();
        cur ^= 1;
    }

    {
        float bv = binp[t];
        #pragma unroll
        for (int r = 0; r < 4; r++) {
            float pv = T[cur][r][t] * bv;
            #pragma unroll
            for (int off = 16; off > 0; off >>= 1)
                pv += __shfl_xor_sync(0xffffffffu, pv, off);
            if (lane == 0) atomicAdd(&tb[r], pv);
        }
    }
    float acc0 = 0.f, acc1 = 0.f, acc2 = 0.f, acc3 = 0.f;
    #pragma unroll 8
    for (int j = 0; j < 256; j++) {
        float w = Win[(size_t)j * 256 + t];
        acc0 = fmaf(T[cur][0][j], w, acc0);
        acc1 = fmaf(T[cur][1][j], w, acc1);
        acc2 = fmaf(T[cur][2][j], w, acc2);
        acc3 = fmaf(T[cur][3][j], w, acc3);
    }
    // store TRANSPOSED: g_WFT[k][slot]
    g_WFT[(size_t)t * 96 + bid * 4 + 0] = acc0;
    g_WFT[(size_t)t * 96 + bid * 4 + 1] = acc1;
    g_WFT[(size_t)t * 96 + bid * 4 + 2] = acc2;
    g_WFT[(size_t)t * 96 + bid * 4 + 3] = acc3;
    __syncthreads();
    if (t < 4) g_bF[bid * 4 + t] = tb[t];
}

// ---------------- fused full-network GEMM + decode, 2-stage cp.async ----------------
__global__ void __launch_bounds__(256) fdec_k(const float* __restrict__ feat) {
    extern __shared__ __align__(16) float sm[];
    float* As   = sm;                          // [2][16][132]
    float* Bsw  = sm + 2 * ATILE;              // [2][16][100]
    float* sbias = sm + 2 * ATILE + 2 * BTILE; // 112
    float* slog = sbias + 112;                 // [128][97]

    const int m0 = blockIdx.x * 128;
    const int b = m0 >> 14;
    const int mm = m0 & (HW - 1);
    const int tid = threadIdx.x;
    const int tx = tid & 15, ty = tid >> 4;

    if (tid < 96) sbias[tid] = g_bF[tid];

    auto load_panel = [&](int p, int s) {
        float* Asd = As + s * ATILE;
        float* Bsd = Bsw + s * BTILE;
        #pragma unroll
        for (int lq = 0; lq < 2; lq++) {
            int idx = tid + lq * 256;
            int k = idx >> 5, c4 = idx & 31;
            cpasync16(smem_addr(&Asd[k * 132 + c4 * 4]),
                      feat + ((size_t)(b * CC + p * 16 + k)) * HW + mm + c4 * 4);
        }
        // weight tile: 16 rows x 24 chunks = 384 chunks
        #pragma unroll
        for (int lq = 0; lq < 2; lq++) {
            int idx = tid + lq * 256;
            if (idx < 384) {
                int k = idx / 24, c = idx % 24;
                cpasync16(smem_addr(&Bsd[k * 100 + c * 4]),
                          g_WFT + (size_t)(p * 16 + k) * 96 + c * 4);
            }
        }
        cp_commit();
    };

    float acc[8][6];
    #pragma unroll
    for (int i = 0; i < 8; i++)
        #pragma unroll
        for (int j = 0; j < 6; j++) acc[i][j] = 0.f;

    load_panel(0, 0);

    #pragma unroll 1
    for (int p = 0; p < 16; p++) {
        cp_wait<0>();
        __syncthreads();
        if (p + 1 < 16) load_panel(p + 1, (p + 1) & 1);
        const float* Asd = As + (p & 1) * ATILE;
        const float* Bsd = Bsw + (p & 1) * BTILE;

        #pragma unroll
        for (int kk = 0; kk < 16; kk++) {
            float4 a0 = *(const float4*)&Asd[kk * 132 + ty * 8];
            float4 a1 = *(const float4*)&Asd[kk * 132 + ty * 8 + 4];
            float a[8] = {a0.x, a0.y, a0.z, a0.w, a1.x, a1.y, a1.z, a1.w};
            float bv[6];
            #pragma unroll
            for (int j = 0; j < 6; j++) bv[j] = Bsd[kk * 100 + tx + 16 * j];
            #pragma unroll
            for (int i = 0; i < 8; i++)
                #pragma unroll
                for (int j = 0; j < 6; j++)
                    acc[i][j] = fmaf(a[i], bv[j], acc[i][j]);
        }
        __syncthreads();
    }

    #pragma unroll
    for (int i = 0; i < 8; i++)
        #pragma unroll
        for (int j = 0; j < 6; j++) {
            int col = tx + 16 * j;
            slog[(ty * 8 + i) * 97 + col] = acc[i][j] + sbias[col];
        }
    __syncthreads();

    if (tid < 128) {
        const float* lg = &slog[tid * 97];
        float objp = sigmoidf_(lg[84]);
        float best = -1.f; int bl = 0;
        #pragma unroll 4
        for (int c = 0; c < NCLS; c++) {
            float pr = sigmoidf_(lg[c]) * objp;
            if (pr > best) { best = pr; bl = c; }
        }
        int n = m0 + tid;
        g_score[n] = best;
        g_label[n] = bl;
        int hw = n & (HW - 1);
        int h = hw >> 7, w = hw & 127;
        float px = (w + 0.5f) * 8.f;
        float py = (h + 0.5f) * 8.f;
        float l = expf(lg[80]) * 8.f;
        float t = expf(lg[81]) * 8.f;
        float r = expf(lg[82]) * 8.f;
        float d = expf(lg[83]) * 8.f;
        g_boxes[(size_t)n * 4 + 0] = px - l;
        g_boxes[(size_t)n * 4 + 1] = py - t;
        g_boxes[(size_t)n * 4 + 2] = px + r;
        g_boxes[(size_t)n * 4 + 3] = py + d;
    }
}

// ---------------- exact top-1000: warp-aggregated histograms + compact + bitonic ----------------
__global__ void topk_k() {
    __shared__ int hist[256];
    __shared__ int s_b1, s_n1, s_thr, s_cnt;
    __shared__ unsigned long long skey[4096];
    int b = blockIdx.x;
    int tid = threadIdx.x;   // 1024
    int lane = tid & 31;

    if (tid < 256) hist[tid] = 0;
    __syncthreads();
    for (int i = tid; i < HW; i += 1024) {
        unsigned u = __float_as_uint(g_score[b * HW + i]);
        int bin = u >> 24;
        unsigned mm = __match_any_sync(0xffffffffu, bin);
        if (lane == (__ffs(mm) - 1)) atomicAdd(&hist[bin], __popc(mm));
    }
    __syncthreads();
    if (tid == 0) {
        int acc = 0; int bin = 255;
        for (; bin > 0; bin--) { if (acc + hist[bin] >= NMS_CAND) break; acc += hist[bin]; }
        s_b1 = bin; s_n1 = acc;
    }
    __syncthreads();
    int b1 = s_b1, n1 = s_n1;
    if (tid < 256) hist[tid] = 0;
    __syncthreads();
    for (int i = tid; i < HW; i += 1024) {
        unsigned u = __float_as_uint(g_score[b * HW + i]);
        bool sel = ((int)(u >> 24) == b1);
        unsigned active = __ballot_sync(0xffffffffu, sel);
        if (sel) {
            int bin2 = (u >> 16) & 255;
            unsigned mm = __match_any_sync(active, bin2);
            if (lane == (__ffs(mm) - 1)) atomicAdd(&hist[bin2], __popc(mm));
        }
    }
    __syncthreads();
    if (tid == 0) {
        int acc = n1; int bin = 255;
        for (; bin > 0; bin--) { if (acc + hist[bin] >= NMS_CAND) break; acc += hist[bin]; }
        s_thr = (b1 << 8) | bin;
        s_cnt = 0;
    }
    __syncthreads();
    unsigned thr = (unsigned)s_thr;
    for (int i = tid; i < HW; i += 1024) {
        unsigned u = __float_as_uint(g_score[b * HW + i]);
        bool pass = (u >> 16) >= thr;
        unsigned bal = __ballot_sync(0xffffffffu, pass);
        int base = 0;
        if (lane == 0 && bal) base = atomicAdd(&s_cnt, __popc(bal));
        base = __shfl_sync(0xffffffffu, base, 0);
        if (pass) {
            int pos = base + __popc(bal & ((1u << lane) - 1u));
            if (pos < 4096)
                skey[pos] = ((unsigned long long)(~u) << 32) | (unsigned)i;
        }
    }
    __syncthreads();
    int cnt = s_cnt < 4096 ? s_cnt : 4096;
    for (int i = tid; i < 4096; i += 1024)
        if (i >= cnt) skey[i] = 0xFFFFFFFFFFFFFFFFull;
    __syncthreads();

    for (int k = 2; k <= 4096; k <<= 1) {
        for (int j = k >> 1; j > 0; j >>= 1) {
            #pragma unroll
            for (int l = 0; l < 4; l++) {
                int i = tid + l * 1024;
                int ixj = i ^ j;
                if (ixj > i) {
                    bool up = ((i & k) == 0);
                    unsigned long long a = skey[i], c = skey[ixj];
                    if (up ? (a > c) : (a < c)) { skey[i] = c; skey[ixj] = a; }
                }
            }
            __syncthreads();
        }
    }

    if (tid < NMS_CAND) {
        unsigned long long key = skey[tid];
        int idx = (int)(unsigned)key;
        float s = __uint_as_float(~(unsigned)(key >> 32));
        int g = b * HW + idx;
        int dst = b * NMS_CAND + tid;
        g_cand_sc[dst] = s;
        g_cand_lab[dst] = g_label[g];
        #pragma unroll
        for (int q = 0; q < 4; q++)
            g_cand_box[dst * 4 + q] = g_boxes[(size_t)g * 4 + q];
    }
}

// ---------------- NMS (chip-parallel mask + 1-warp reduce) ----------------
__global__ void nms_mask_k() {
    int i = blockIdx.x;
    int b = blockIdx.y;
    int j = threadIdx.x;
    const float* bi = &g_cand_box[(b * NMS_CAND + i) * 4];
    float ix1 = bi[0], iy1 = bi[1], ix2 = bi[2], iy2 = bi[3];
    float ai = fmaxf(ix2 - ix1, 0.f) * fmaxf(iy2 - iy1, 0.f);
    bool pred = false;
    if (j < NMS_CAND && j > i) {
        const float* bj = &g_cand_box[(b * NMS_CAND + j) * 4];
        float aj = fmaxf(bj[2] - bj[0], 0.f) * fmaxf(bj[3] - bj[1], 0.f);
        float xx1 = fmaxf(ix1, bj[0]), yy1 = fmaxf(iy1, bj[1]);
        float xx2 = fminf(ix2, bj[2]), yy2 = fminf(iy2, bj[3]);
        float iw = fmaxf(xx2 - xx1, 0.f), ih = fmaxf(yy2 - yy1, 0.f);
        float inter = iw * ih;
        float iou = inter / (ai + aj - inter + 1e-6f);
        pred = iou > 0.65f;
    }
    unsigned m = __ballot_sync(0xffffffffu, pred);
    if ((j & 31) == 0)
        g_mask[((size_t)(b * NMS_CAND + i)) * 32 + (j >> 5)] = m;
}

__global__ void nms_reduce_k() {
    extern __shared__ unsigned smask[];
    int b = blockIdx.x;
    for (int t = threadIdx.x; t < NMS_CAND * 32; t += 1024)
        smask[t] = g_mask[(size_t)b * NMS_CAND * 32 + t];
    __syncthreads();
    if (threadIdx.x < 32) {
        int lane = threadIdx.x;
        unsigned removed = 0u;
        for (int i = 0; i < NMS_CAND; i++) {
            unsigned rw = __shfl_sync(0xffffffffu, removed, i >> 5);
            if (!((rw >> (i & 31)) & 1u))
                removed |= smask[i * 32 + lane];
        }
        g_keep[b * 32 + lane] = ~removed;
    }
}

// ---------------- final select ----------------
__global__ void select_k(float* __restrict__ out) {
    __shared__ int ps[1024];
    __shared__ int s_total;
    int b = blockIdx.x;
    int tid = threadIdx.x;
    int kept = 0;
    if (tid < NMS_CAND)
        kept = (g_keep[b * 32 + (tid >> 5)] >> (tid & 31)) & 1;
    ps[tid] = kept;
    __syncthreads();
    for (int off = 1; off < 1024; off <<= 1) {
        int v = (tid >= off) ? ps[tid - off] : 0;
        __syncthreads();
        ps[tid] += v;
        __syncthreads();
    }
    if (tid == 1023) s_total = ps[1023];
    __syncthreads();
    int total = s_total;
    if (tid < NMS_CAND) {
        int excl = ps[tid] - kept;
        int pos = kept ? excl : total + (tid - excl);
        if (pos < MAX_DET) {
            int src = b * NMS_CAND + tid;
            out[(b * MAX_DET + pos) * 4 + 0] = g_cand_box[src * 4 + 0];
            out[(b * MAX_DET + pos) * 4 + 1] = g_cand_box[src * 4 + 1];
            out[(b * MAX_DET + pos) * 4 + 2] = g_cand_box[src * 4 + 2];
            out[(b * MAX_DET + pos) * 4 + 3] = g_cand_box[src * 4 + 3];
            out[BB * MAX_DET * 4 + b * MAX_DET + pos] = kept ? g_cand_sc[src] : 0.f;
            out[BB * MAX_DET * 5 + b * MAX_DET + pos] = (float)g_cand_lab[src];
        }
    }
}

// ---------------- launch ----------------
extern "C" void kernel_launch(void* const* d_in, const int* in_sizes, int n_in,
                              void* d_out, int out_size) {
    (void)in_sizes; (void)n_in; (void)out_size;
    const float* feat = (const float*)d_in[0];
    const float* cls_w_in  = (const float*)d_in[1];
    const float* cls_b_in  = (const float*)d_in[2];
    const float* cls_w_hid = (const float*)d_in[3];
    const float* cls_b_hid = (const float*)d_in[4];
    const float* cls_w_out = (const float*)d_in[5];
    const float* cls_b_out = (const float*)d_in[6];
    const float* obj_w_in  = (const float*)d_in[7];
    const float* obj_b_in  = (const float*)d_in[8];
    const float* obj_w_hid = (const float*)d_in[9];
    const float* obj_b_hid = (const float*)d_in[10];
    const float* obj_w_out = (const float*)d_in[11];
    const float* obj_b_out = (const float*)d_in[12];
    const float* box_w_in  = (const float*)d_in[13];
    const float* box_b_in  = (const float*)d_in[14];
    const float* box_w_hid = (const float*)d_in[15];
    const float* box_b_hid = (const float*)d_in[16];
    const float* box_w_out = (const float*)d_in[17];
    const float* box_b_out = (const float*)d_in[18];
    float* out = (float*)d_out;

    const int fdec_smem = (2 * ATILE + 2 * BTILE + 112 + 128 * 97) * (int)sizeof(float);
    cudaFuncSetAttribute(fdec_k, cudaFuncAttributeMaxDynamicSharedMemorySize, fdec_smem);
    cudaFuncSetAttribute(nms_reduce_k, cudaFuncAttributeMaxDynamicSharedMemorySize, 131072);

    // 0) full-network composition -> WFT[256][96], bF[96]
    wfull_k<<<24, 256>>>(cls_w_in, cls_b_in, cls_w_hid, cls_b_hid, cls_w_out, cls_b_out,
                         obj_w_in, obj_b_in, obj_w_hid, obj_b_hid, obj_w_out, obj_b_out,
                         box_w_in, box_b_in, box_w_hid, box_b_hid, box_w_out, box_b_out);

    // 1) fused full-network GEMM + decode (pipelined)
    fdec_k<<<MPIX / 128, 256, fdec_smem>>>(feat);

    // 2) exact per-batch top-1000
    topk_k<<<BB, 1024>>>();

    // 3) NMS (chip-parallel)
    nms_mask_k<<<dim3(NMS_CAND, BB), 1024>>>();
    nms_reduce_k<<<BB, 1024, NMS_CAND * 32 * (int)sizeof(unsigned)>>>();

    // 4) final top-100 select
    select_k<<<BB, 1024>>>(out);
}

// round 17
// speedup vs baseline: 2.0917x; 1.1063x over previous
#include <cuda_runtime.h>
#include <cstdint>
#include <cstddef>

// ---------------- problem constants ----------------
#define BB 2
#define CC 256
#define HW 16384
#define MPIX 32768
#define NCLS 80
#define NMS_CAND 1000
#define MAX_DET 100
#define ATILE (16 * 132)
#define BTILE (16 * 100)

// ---------------- scratch ----------------
__device__ float g_WFT[256 * 96];    // transposed full weights: [k][slot]
__device__ float g_bF[96];
__device__ float g_score[MPIX];
__device__ int   g_label[MPIX];
__device__ float g_boxes[(size_t)MPIX * 4];
__device__ float g_cand_sc[BB * NMS_CAND];
__device__ int   g_cand_lab[BB * NMS_CAND];
__device__ float g_cand_box[BB * NMS_CAND * 4];
__device__ unsigned g_mask[(size_t)BB * NMS_CAND * 32];

__device__ __forceinline__ float sigmoidf_(float x) { return 1.f / (1.f + expf(-x)); }
__device__ __forceinline__ unsigned smem_addr(const void* p) {
    return (unsigned)__cvta_generic_to_shared(p);
}
__device__ __forceinline__ void cpasync16(unsigned dst, const float* src) {
    asm volatile("cp.async.cg.shared.global [%0], [%1], 16;\n" :: "r"(dst), "l"(src));
}
__device__ __forceinline__ void cp_commit() {
    asm volatile("cp.async.commit_group;\n" ::: "memory");
}
template <int N>
__device__ __forceinline__ void cp_wait() {
    asm volatile("cp.async.wait_group %0;\n" :: "n"(N) : "memory");
}
__device__ __forceinline__ void ffma2(unsigned long long& d, unsigned long long a, unsigned long long b) {
    asm("fma.rn.f32x2 %0, %1, %2, %0;" : "+l"(d) : "l"(a), "l"(b));
}
__device__ __forceinline__ unsigned long long dup2(float x) {
    unsigned long long r;
    asm("mov.b64 %0, {%1, %1};" : "=l"(r) : "f"(x));
    return r;
}
__device__ __forceinline__ void unpack2(unsigned long long v, float& lo, float& hi) {
    asm("mov.b64 {%0, %1}, %2;" : "=f"(lo), "=f"(hi) : "l"(v));
}

// ---------------- full-network composition: cp.async-streamed weight chain ----------------
// T rows (4 per block) absorb (I+W3)(I+W2)(I+W1)(I+W0) then multiply W_in, with biases.
// 40 chunks of 32 rows streamed through a 4-stage smem pipeline.
#define WCH 8192                       // floats per 32-row chunk
#define WFULL_SMEM (4 * WCH * 4)       // 131072 B dynamic
__global__ void __launch_bounds__(256) wfull_k(
    const float* __restrict__ cwin, const float* __restrict__ cbin,
    const float* __restrict__ cwh,  const float* __restrict__ cbh,
    const float* __restrict__ cwo,  const float* __restrict__ cbo,
    const float* __restrict__ owin, const float* __restrict__ obin,
    const float* __restrict__ owh,  const float* __restrict__ obh,
    const float* __restrict__ owo,  const float* __restrict__ obo,
    const float* __restrict__ bwin, const float* __restrict__ bbin,
    const float* __restrict__ bwh,  const float* __restrict__ bbh,
    const float* __restrict__ bwo,  const float* __restrict__ bbo)
{
    extern __shared__ __align__(16) float Wst[];   // [4][WCH]
    __shared__ float T[2][4][256];
    __shared__ float tb[4];
    const int bid = blockIdx.x;   // 0..23 -> slots 4*bid..4*bid+3
    const int t = threadIdx.x;    // 256
    const int lane = t & 31;

    const float *Whid, *bhid, *Win, *binp;
    if (bid < 20)      { Whid = cwh; bhid = cbh; Win = cwin; binp = cbin; }
    else if (bid == 20){ Whid = bwh; bhid = bbh; Win = bwin; binp = bbin; }
    else               { Whid = owh; bhid = obh; Win = owin; binp = obin; }

    auto srcW = [&](int s) -> const float* {
        return (s < 4) ? (Whid + (size_t)(3 - s) * 65536) : Win;
    };
    auto load_chunk = [&](int g, int slot) {
        int s = g >> 3, c = g & 7;
        const float* W = srcW(s);
        float* dst = Wst + slot * WCH;
        #pragma unroll
        for (int lq = 0; lq < 8; lq++) {
            int i = t + lq * 256;
            int row = i >> 6, c4 = i & 63;
            cpasync16(smem_addr(&dst[row * 256 + c4 * 4]),
                      W + (size_t)(c * 32 + row) * 256 + c4 * 4);
        }
        cp_commit();
    };

    // init T + tb from out-layer
    #pragma unroll
    for (int r = 0; r < 4; r++) {
        int s = bid * 4 + r;
        float v = 0.f;
        if (s < 80)        v = cwo[(size_t)s * 256 + t];
        else if (s < 84)   v = bwo[(size_t)(s - 80) * 256 + t];
        else if (s == 84)  v = owo[t];
        T[0][r][t] = v;
    }
    if (t < 4) {
        int s = bid * 4 + t;
        float bv = 0.f;
        if (s < 80)        bv = cbo[s];
        else if (s < 84)   bv = bbo[s - 80];
        else if (s == 84)  bv = obo[0];
        tb[t] = bv;
    }

    load_chunk(0, 0);
    load_chunk(1, 1);
    load_chunk(2, 2);
    __syncthreads();

    int cur = 0;
    float a0 = 0.f, a1 = 0.f, a2 = 0.f, a3 = 0.f;
    #pragma unroll 1
    for (int g = 0; g < 40; g++) {
        const int s = g >> 3, c = g & 7;
        if (c == 0) {
            // absorb this stage's bias using the finalized current T
            const float* bl = (s < 4) ? (bhid + (3 - s) * 256) : binp;
            float blv = bl[t];
            #pragma unroll
            for (int r = 0; r < 4; r++) {
                float pv = T[cur][r][t] * blv;
                #pragma unroll
                for (int off = 16; off > 0; off >>= 1)
                    pv += __shfl_xor_sync(0xffffffffu, pv, off);
                if (lane == 0) atomicAdd(&tb[r], pv);
            }
        }
        if (g < 37) cp_wait<2>(); else if (g == 37) cp_wait<2>();
        else if (g == 38) cp_wait<1>(); else cp_wait<0>();
        __syncthreads();
        if (g + 3 < 40) load_chunk(g + 3, (g + 3) & 3);
        const float* Wc = Wst + (g & 3) * WCH;
        const int j0 = c * 32;
        #pragma unroll 8
        for (int jj = 0; jj < 32; jj++) {
            float w = Wc[jj * 256 + t];
            int j = j0 + jj;
            a0 = fmaf(T[cur][0][j], w, a0);
            a1 = fmaf(T[cur][1][j], w, a1);
            a2 = fmaf(T[cur][2][j], w, a2);
            a3 = fmaf(T[cur][3][j], w, a3);
        }
        if (c == 7) {
            if (s < 4) {
                T[cur ^ 1][0][t] = T[cur][0][t] + a0;
                T[cur ^ 1][1][t] = T[cur][1][t] + a1;
                T[cur ^ 1][2][t] = T[cur][2][t] + a2;
                T[cur ^ 1][3][t] = T[cur][3][t] + a3;
                cur ^= 1;
            } else {
                g_WFT[(size_t)t * 96 + bid * 4 + 0] = a0;
                g_WFT[(size_t)t * 96 + bid * 4 + 1] = a1;
                g_WFT[(size_t)t * 96 + bid * 4 + 2] = a2;
                g_WFT[(size_t)t * 96 + bid * 4 + 3] = a3;
            }
            a0 = a1 = a2 = a3 = 0.f;
        }
    }
    __syncthreads();
    if (t < 4) g_bF[bid * 4 + t] = tb[t];
}

// ---------------- fused full-network GEMM + decode, 2-stage cp.async, f32x2 ----------------
__global__ void __launch_bounds__(256) fdec_k(const float* __restrict__ feat) {
    extern __shared__ __align__(16) float sm[];
    float* As   = sm;                          // [2][16][132]
    float* Bsw  = sm + 2 * ATILE;              // [2][16][100]
    float* sbias = sm + 2 * ATILE + 2 * BTILE; // 112
    float* slog = sbias + 112;                 // [128][97]

    const int m0 = blockIdx.x * 128;
    const int b = m0 >> 14;
    const int mm = m0 & (HW - 1);
    const int tid = threadIdx.x;
    const int tx = tid & 15, ty = tid >> 4;

    if (tid < 96) sbias[tid] = g_bF[tid];

    auto load_panel = [&](int p, int s) {
        float* Asd = As + s * ATILE;
        float* Bsd = Bsw + s * BTILE;
        #pragma unroll
        for (int lq = 0; lq < 2; lq++) {
            int idx = tid + lq * 256;
            int k = idx >> 5, c4 = idx & 31;
            cpasync16(smem_addr(&Asd[k * 132 + c4 * 4]),
                      feat + ((size_t)(b * CC + p * 16 + k)) * HW + mm + c4 * 4);
        }
        #pragma unroll
        for (int lq = 0; lq < 2; lq++) {
            int idx = tid + lq * 256;
            if (idx < 384) {
                int k = idx / 24, c = idx % 24;
                cpasync16(smem_addr(&Bsd[k * 100 + c * 4]),
                          g_WFT + (size_t)(p * 16 + k) * 96 + c * 4);
            }
        }
        cp_commit();
    };

    unsigned long long acc2[4][6];
    #pragma unroll
    for (int p = 0; p < 4; p++)
        #pragma unroll
        for (int j = 0; j < 6; j++) acc2[p][j] = 0ull;

    load_panel(0, 0);

    #pragma unroll 1
    for (int p = 0; p < 16; p++) {
        cp_wait<0>();
        __syncthreads();
        if (p + 1 < 16) load_panel(p + 1, (p + 1) & 1);
        const float* Asd = As + (p & 1) * ATILE;
        const float* Bsd = Bsw + (p & 1) * BTILE;

        #pragma unroll
        for (int kk = 0; kk < 16; kk++) {
            ulonglong2 aa0 = *(const ulonglong2*)&Asd[kk * 132 + ty * 8];
            ulonglong2 aa1 = *(const ulonglong2*)&Asd[kk * 132 + ty * 8 + 4];
            unsigned long long ap[4] = {aa0.x, aa0.y, aa1.x, aa1.y};
            unsigned long long bd[6];
            #pragma unroll
            for (int j = 0; j < 6; j++) bd[j] = dup2(Bsd[kk * 100 + tx + 16 * j]);
            #pragma unroll
            for (int q = 0; q < 4; q++)
                #pragma unroll
                for (int j = 0; j < 6; j++)
                    ffma2(acc2[q][j], ap[q], bd[j]);
        }
        __syncthreads();
    }

    #pragma unroll
    for (int q = 0; q < 4; q++)
        #pragma unroll
        for (int j = 0; j < 6; j++) {
            int col = tx + 16 * j;
            float lo, hi;
            unpack2(acc2[q][j], lo, hi);
            slog[(ty * 8 + 2 * q) * 97 + col] = lo + sbias[col];
            slog[(ty * 8 + 2 * q + 1) * 97 + col] = hi + sbias[col];
        }
    __syncthreads();

    if (tid < 128) {
        const float* lg = &slog[tid * 97];
        float objp = sigmoidf_(lg[84]);
        float best = -1.f; int bl = 0;
        #pragma unroll 4
        for (int c = 0; c < NCLS; c++) {
            float pr = sigmoidf_(lg[c]) * objp;
            if (pr > best) { best = pr; bl = c; }
        }
        int n = m0 + tid;
        g_score[n] = best;
        g_label[n] = bl;
        int hw = n & (HW - 1);
        int h = hw >> 7, w = hw & 127;
        float px = (w + 0.5f) * 8.f;
        float py = (h + 0.5f) * 8.f;
        float l = expf(lg[80]) * 8.f;
        float t = expf(lg[81]) * 8.f;
        float r = expf(lg[82]) * 8.f;
        float d = expf(lg[83]) * 8.f;
        g_boxes[(size_t)n * 4 + 0] = px - l;
        g_boxes[(size_t)n * 4 + 1] = py - t;
        g_boxes[(size_t)n * 4 + 2] = px + r;
        g_boxes[(size_t)n * 4 + 3] = py + d;
    }
}

// ---------------- exact top-1000: warp-aggregated histograms + compact + bitonic ----------------
__global__ void topk_k() {
    __shared__ int hist[256];
    __shared__ int s_b1, s_n1, s_thr, s_cnt;
    __shared__ unsigned long long skey[4096];
    int b = blockIdx.x;
    int tid = threadIdx.x;   // 1024
    int lane = tid & 31;

    if (tid < 256) hist[tid] = 0;
    __syncthreads();
    for (int i = tid; i < HW; i += 1024) {
        unsigned u = __float_as_uint(g_score[b * HW + i]);
        int bin = u >> 24;
        unsigned mm = __match_any_sync(0xffffffffu, bin);
        if (lane == (__ffs(mm) - 1)) atomicAdd(&hist[bin], __popc(mm));
    }
    __syncthreads();
    if (tid == 0) {
        int acc = 0; int bin = 255;
        for (; bin > 0; bin--) { if (acc + hist[bin] >= NMS_CAND) break; acc += hist[bin]; }
        s_b1 = bin; s_n1 = acc;
    }
    __syncthreads();
    int b1 = s_b1, n1 = s_n1;
    if (tid < 256) hist[tid] = 0;
    __syncthreads();
    for (int i = tid; i < HW; i += 1024) {
        unsigned u = __float_as_uint(g_score[b * HW + i]);
        bool sel = ((int)(u >> 24) == b1);
        unsigned active = __ballot_sync(0xffffffffu, sel);
        if (sel) {
            int bin2 = (u >> 16) & 255;
            unsigned mm = __match_any_sync(active, bin2);
            if (lane == (__ffs(mm) - 1)) atomicAdd(&hist[bin2], __popc(mm));
        }
    }
    __syncthreads();
    if (tid == 0) {
        int acc = n1; int bin = 255;
        for (; bin > 0; bin--) { if (acc + hist[bin] >= NMS_CAND) break; acc += hist[bin]; }
        s_thr = (b1 << 8) | bin;
        s_cnt = 0;
    }
    __syncthreads();
    unsigned thr = (unsigned)s_thr;
    for (int i = tid; i < HW; i += 1024) {
        unsigned u = __float_as_uint(g_score[b * HW + i]);
        bool pass = (u >> 16) >= thr;
        unsigned bal = __ballot_sync(0xffffffffu, pass);
        int base = 0;
        if (lane == 0 && bal) base = atomicAdd(&s_cnt, __popc(bal));
        base = __shfl_sync(0xffffffffu, base, 0);
        if (pass) {
            int pos = base + __popc(bal & ((1u << lane) - 1u));
            if (pos < 4096)
                skey[pos] = ((unsigned long long)(~u) << 32) | (unsigned)i;
        }
    }
    __syncthreads();
    int cnt = s_cnt < 4096 ? s_cnt : 4096;
    for (int i = tid; i < 4096; i += 1024)
        if (i >= cnt) skey[i] = 0xFFFFFFFFFFFFFFFFull;
    __syncthreads();

    for (int k = 2; k <= 4096; k <<= 1) {
        for (int j = k >> 1; j > 0; j >>= 1) {
            #pragma unroll
            for (int l = 0; l < 4; l++) {
                int i = tid + l * 1024;
                int ixj = i ^ j;
                if (ixj > i) {
                    bool up = ((i & k) == 0);
                    unsigned long long a = skey[i], c = skey[ixj];
                    if (up ? (a > c) : (a < c)) { skey[i] = c; skey[ixj] = a; }
                }
            }
            __syncthreads();
        }
    }

    if (tid < NMS_CAND) {
        unsigned long long key = skey[tid];
        int idx = (int)(unsigned)key;
        float s = __uint_as_float(~(unsigned)(key >> 32));
        int g = b * HW + idx;
        int dst = b * NMS_CAND + tid;
        g_cand_sc[dst] = s;
        g_cand_lab[dst] = g_label[g];
        #pragma unroll
        for (int q = 0; q < 4; q++)
            g_cand_box[dst * 4 + q] = g_boxes[(size_t)g * 4 + q];
    }
}

// ---------------- NMS mask (chip-parallel) ----------------
__global__ void nms_mask_k() {
    int i = blockIdx.x;
    int b = blockIdx.y;
    int j = threadIdx.x;
    const float* bi = &g_cand_box[(b * NMS_CAND + i) * 4];
    float ix1 = bi[0], iy1 = bi[1], ix2 = bi[2], iy2 = bi[3];
    float ai = fmaxf(ix2 - ix1, 0.f) * fmaxf(iy2 - iy1, 0.f);
    bool pred = false;
    if (j < NMS_CAND && j > i) {
        const float* bj = &g_cand_box[(b * NMS_CAND + j) * 4];
        float aj = fmaxf(bj[2] - bj[0], 0.f) * fmaxf(bj[3] - bj[1], 0.f);
        float xx1 = fmaxf(ix1, bj[0]), yy1 = fmaxf(iy1, bj[1]);
        float xx2 = fminf(ix2, bj[2]), yy2 = fminf(iy2, bj[3]);
        float iw = fmaxf(xx2 - xx1, 0.f), ih = fmaxf(yy2 - yy1, 0.f);
        float inter = iw * ih;
        float iou = inter / (ai + aj - inter + 1e-6f);
        pred = iou > 0.65f;
    }
    unsigned m = __ballot_sync(0xffffffffu, pred);
    if ((j & 31) == 0)
        g_mask[((size_t)(b * NMS_CAND + i)) * 32 + (j >> 5)] = m;
}

// ---------------- merged sequential reduce + final select ----------------
__global__ void reduce_select_k(float* __restrict__ out) {
    extern __shared__ unsigned smask[];   // 1000*32 = 128000 B
    __shared__ unsigned keepw[32];
    __shared__ int ps[1024];
    __shared__ int s_total;
    int b = blockIdx.x;
    int tid = threadIdx.x;

    for (int t = tid; t < NMS_CAND * 32; t += 1024)
        smask[t] = g_mask[(size_t)b * NMS_CAND * 32 + t];
    __syncthreads();
    if (tid < 32) {
        int lane = tid;
        unsigned removed = 0u;
        for (int i = 0; i < NMS_CAND; i++) {
            unsigned rw = __shfl_sync(0xffffffffu, removed, i >> 5);
            if (!((rw >> (i & 31)) & 1u))
                removed |= smask[i * 32 + lane];
        }
        keepw[lane] = ~removed;
    }
    __syncthreads();

    int kept = 0;
    if (tid < NMS_CAND)
        kept = (keepw[tid >> 5] >> (tid & 31)) & 1;
    ps[tid] = kept;
    __syncthreads();
    for (int off = 1; off < 1024; off <<= 1) {
        int v = (tid >= off) ? ps[tid - off] : 0;
        __syncthreads();
        ps[tid] += v;
        __syncthreads();
    }
    if (tid == 1023) s_total = ps[1023];
    __syncthreads();
    int total = s_total;
    if (tid < NMS_CAND) {
        int excl = ps[tid] - kept;
        int pos = kept ? excl : total + (tid - excl);
        if (pos < MAX_DET) {
            int src = b * NMS_CAND + tid;
            out[(b * MAX_DET + pos) * 4 + 0] = g_cand_box[src * 4 + 0];
            out[(b * MAX_DET + pos) * 4 + 1] = g_cand_box[src * 4 + 1];
            out[(b * MAX_DET + pos) * 4 + 2] = g_cand_box[src * 4 + 2];
            out[(b * MAX_DET + pos) * 4 + 3] = g_cand_box[src * 4 + 3];
            out[BB * MAX_DET * 4 + b * MAX_DET + pos] = kept ? g_cand_sc[src] : 0.f;
            out[BB * MAX_DET * 5 + b * MAX_DET + pos] = (float)g_cand_lab[src];
        }
    }
}

// ---------------- launch ----------------
extern "C" void kernel_launch(void* const* d_in, const int* in_sizes, int n_in,
                              void* d_out, int out_size) {
    (void)in_sizes; (void)n_in; (void)out_size;
    const float* feat = (const float*)d_in[0];
    const float* cls_w_in  = (const float*)d_in[1];
    const float* cls_b_in  = (const float*)d_in[2];
    const float* cls_w_hid = (const float*)d_in[3];
    const float* cls_b_hid = (const float*)d_in[4];
    const float* cls_w_out = (const float*)d_in[5];
    const float* cls_b_out = (const float*)d_in[6];
    const float* obj_w_in  = (const float*)d_in[7];
    const float* obj_b_in  = (const float*)d_in[8];
    const float* obj_w_hid = (const float*)d_in[9];
    const float* obj_b_hid = (const float*)d_in[10];
    const float* obj_w_out = (const float*)d_in[11];
    const float* obj_b_out = (const float*)d_in[12];
    const float* box_w_in  = (const float*)d_in[13];
    const float* box_b_in  = (const float*)d_in[14];
    const float* box_w_hid = (const float*)d_in[15];
    const float* box_b_hid = (const float*)d_in[16];
    const float* box_w_out = (const float*)d_in[17];
    const float* box_b_out = (const float*)d_in[18];
    float* out = (float*)d_out;

    const int fdec_smem = (2 * ATILE + 2 * BTILE + 112 + 128 * 97) * (int)sizeof(float);
    cudaFuncSetAttribute(wfull_k, cudaFuncAttributeMaxDynamicSharedMemorySize, WFULL_SMEM);
    cudaFuncSetAttribute(fdec_k, cudaFuncAttributeMaxDynamicSharedMemorySize, fdec_smem);
    cudaFuncSetAttribute(reduce_select_k, cudaFuncAttributeMaxDynamicSharedMemorySize, 131072);

    // 0) full-network composition -> WFT[256][96], bF[96]
    wfull_k<<<24, 256, WFULL_SMEM>>>(cls_w_in, cls_b_in, cls_w_hid, cls_b_hid, cls_w_out, cls_b_out,
                                     obj_w_in, obj_b_in, obj_w_hid, obj_b_hid, obj_w_out, obj_b_out,
                                     box_w_in, box_b_in, box_w_hid, box_b_hid, box_w_out, box_b_out);

    // 1) fused full-network GEMM + decode (pipelined, f32x2)
    fdec_k<<<MPIX / 128, 256, fdec_smem>>>(feat);

    // 2) exact per-batch top-1000
    topk_k<<<BB, 1024>>>();

    // 3) NMS mask (chip-parallel)
    nms_mask_k<<<dim3(NMS_CAND, BB), 1024>>>();

    // 4) merged reduce + select
    reduce_select_k<<<BB, 1024, NMS_CAND * 32 * (int)sizeof(unsigned)>>>(out);
}